// round 1
// baseline (speedup 1.0000x reference)
#include <cuda_runtime.h>

#define NN 100000
#define EE 1600000
#define GG 512
#define HH 128
#define NB 98  // ceil(NN/1024)

// ---------------- scratch (device globals: no allocation allowed) ----------
__device__ float g_bufA[NN * HH];   // GEMM output (messages y)
__device__ float g_bufB[NN * HH];   // SpMM output (hidden h)
__device__ int   g_cnt_in[NN];
__device__ int   g_cnt_out[NN];
__device__ int   g_row_ptr[NN + 1];
__device__ int   g_cursor[NN];
__device__ int   g_col[EE];         // src indices grouped by dst (CSR-by-dst)
__device__ float g_norm_in[NN];
__device__ float g_norm_out[NN];
__device__ float g_graph[GG * HH];  // readout accumulator
__device__ int   g_bsum[128];

// ---------------- build kernels -------------------------------------------
__global__ void k_zero() {
    int i = blockIdx.x * blockDim.x + threadIdx.x;
    if (i < NN) { g_cnt_in[i] = 0; g_cnt_out[i] = 0; g_cursor[i] = 0; }
    if (i < GG * HH) g_graph[i] = 0.f;
}

__global__ void k_hist(const int* __restrict__ src, const int* __restrict__ dst) {
    int i = blockIdx.x * blockDim.x + threadIdx.x;
    if (i < EE) {
        atomicAdd(&g_cnt_out[src[i]], 1);
        atomicAdd(&g_cnt_in[dst[i]], 1);
    }
}

__global__ void k_norm() {
    int i = blockIdx.x * blockDim.x + threadIdx.x;
    if (i < NN) {
        g_norm_out[i] = rsqrtf(fmaxf((float)g_cnt_out[i], 1.f));
        g_norm_in[i]  = rsqrtf(fmaxf((float)g_cnt_in[i], 1.f));
    }
}

__global__ void k_scan1() {
    __shared__ int s[1024];
    int t = threadIdx.x;
    int i = blockIdx.x * 1024 + t;
    int v = (i < NN) ? g_cnt_in[i] : 0;
    s[t] = v;
    __syncthreads();
    for (int off = 1; off < 1024; off <<= 1) {
        int add = (t >= off) ? s[t - off] : 0;
        __syncthreads();
        s[t] += add;
        __syncthreads();
    }
    if (i < NN) g_row_ptr[i] = s[t] - v;     // block-local exclusive
    if (t == 1023) g_bsum[blockIdx.x] = s[1023];
}

__global__ void k_scan2() {
    __shared__ int s[128];
    int t = threadIdx.x;
    int v = (t < NB) ? g_bsum[t] : 0;
    s[t] = v;
    __syncthreads();
    for (int off = 1; off < 128; off <<= 1) {
        int add = (t >= off) ? s[t - off] : 0;
        __syncthreads();
        s[t] += add;
        __syncthreads();
    }
    g_bsum[t] = s[t] - v;                    // exclusive block offsets
}

__global__ void k_scan3() {
    int t = threadIdx.x;
    int i = blockIdx.x * 1024 + t;
    if (i < NN) g_row_ptr[i] += g_bsum[blockIdx.x];
    if (i == 0) g_row_ptr[NN] = EE;
}

__global__ void k_scatter(const int* __restrict__ src, const int* __restrict__ dst) {
    int i = blockIdx.x * blockDim.x + threadIdx.x;
    if (i < EE) {
        int d = dst[i];
        int pos = g_row_ptr[d] + atomicAdd(&g_cursor[d], 1);
        g_col[pos] = src[i];
    }
}

// ---------------- dense GEMM: C[r,:] = norm_out[r] * (A[r,:] @ W) ----------
// BM=128 rows/block, full 128 cols, BK=16, 256 threads, 8x8 per thread.
__global__ __launch_bounds__(256) void k_gemm(const float* __restrict__ A,
                                              const float* __restrict__ W,
                                              float* __restrict__ C) {
    __shared__ float As[16][128];   // transposed: As[k][m]
    __shared__ float Ws[16][128];   // Ws[k][n]
    int tid = threadIdx.x;
    int tx = tid & 15, ty = tid >> 4;
    int row0 = blockIdx.x * 128;

    float acc[8][8];
#pragma unroll
    for (int i = 0; i < 8; i++)
#pragma unroll
        for (int j = 0; j < 8; j++) acc[i][j] = 0.f;

    for (int k0 = 0; k0 < HH; k0 += 16) {
#pragma unroll
        for (int j = 0; j < 2; j++) {       // A tile: 128x16 = 512 float4
            int f = tid * 2 + j;
            int r = f >> 2;
            int c4 = (f & 3) * 4;
            int gr = row0 + r;
            float4 v = make_float4(0.f, 0.f, 0.f, 0.f);
            if (gr < NN) v = *(const float4*)&A[gr * HH + k0 + c4];
            As[c4 + 0][r] = v.x; As[c4 + 1][r] = v.y;
            As[c4 + 2][r] = v.z; As[c4 + 3][r] = v.w;
        }
#pragma unroll
        for (int j = 0; j < 2; j++) {       // W tile: 16x128 = 512 float4
            int f = tid * 2 + j;
            int r = f >> 5;
            int c4 = (f & 31) * 4;
            *(float4*)&Ws[r][c4] = *(const float4*)&W[(k0 + r) * HH + c4];
        }
        __syncthreads();
#pragma unroll
        for (int kk = 0; kk < 16; kk++) {
            float a[8], w[8];
            *(float4*)&a[0] = *(const float4*)&As[kk][ty * 8];
            *(float4*)&a[4] = *(const float4*)&As[kk][ty * 8 + 4];
            *(float4*)&w[0] = *(const float4*)&Ws[kk][tx * 8];
            *(float4*)&w[4] = *(const float4*)&Ws[kk][tx * 8 + 4];
#pragma unroll
            for (int i = 0; i < 8; i++)
#pragma unroll
                for (int j = 0; j < 8; j++)
                    acc[i][j] = fmaf(a[i], w[j], acc[i][j]);
        }
        __syncthreads();
    }

#pragma unroll
    for (int i = 0; i < 8; i++) {
        int gr = row0 + ty * 8 + i;
        if (gr < NN) {
            float sc = g_norm_out[gr];
            float4 o0, o1;
            o0.x = acc[i][0] * sc; o0.y = acc[i][1] * sc;
            o0.z = acc[i][2] * sc; o0.w = acc[i][3] * sc;
            o1.x = acc[i][4] * sc; o1.y = acc[i][5] * sc;
            o1.z = acc[i][6] * sc; o1.w = acc[i][7] * sc;
            *(float4*)&C[gr * HH + tx * 8]     = o0;
            *(float4*)&C[gr * HH + tx * 8 + 4] = o1;
        }
    }
}

// ---------------- SpMM: h[i] = relu(norm_in[i] * sum_{e:dst=i} y[src_e] + b)
// One warp per destination node; lane owns 4 contiguous features (float4).
__global__ void k_spmm(const float* __restrict__ Y, const float* __restrict__ bias,
                       float* __restrict__ Hout,
                       const int* __restrict__ n2g, int fuse) {
    int gw = (blockIdx.x * blockDim.x + threadIdx.x) >> 5;
    int lane = threadIdx.x & 31;
    if (gw >= NN) return;
    int beg = g_row_ptr[gw], end = g_row_ptr[gw + 1];

    float4 acc = make_float4(0.f, 0.f, 0.f, 0.f);
    int e = beg;
    for (; e + 4 <= end; e += 4) {
        int s0 = g_col[e + 0], s1 = g_col[e + 1];
        int s2 = g_col[e + 2], s3 = g_col[e + 3];
        float4 v0 = *(const float4*)&Y[s0 * HH + lane * 4];
        float4 v1 = *(const float4*)&Y[s1 * HH + lane * 4];
        float4 v2 = *(const float4*)&Y[s2 * HH + lane * 4];
        float4 v3 = *(const float4*)&Y[s3 * HH + lane * 4];
        acc.x += (v0.x + v1.x) + (v2.x + v3.x);
        acc.y += (v0.y + v1.y) + (v2.y + v3.y);
        acc.z += (v0.z + v1.z) + (v2.z + v3.z);
        acc.w += (v0.w + v1.w) + (v2.w + v3.w);
    }
    for (; e < end; e++) {
        int s0 = g_col[e];
        float4 v = *(const float4*)&Y[s0 * HH + lane * 4];
        acc.x += v.x; acc.y += v.y; acc.z += v.z; acc.w += v.w;
    }

    float ni = g_norm_in[gw];
    float4 b = *(const float4*)&bias[lane * 4];
    float4 h;
    h.x = fmaxf(fmaf(acc.x, ni, b.x), 0.f);
    h.y = fmaxf(fmaf(acc.y, ni, b.y), 0.f);
    h.z = fmaxf(fmaf(acc.z, ni, b.z), 0.f);
    h.w = fmaxf(fmaf(acc.w, ni, b.w), 0.f);

    if (!fuse) {
        *(float4*)&Hout[gw * HH + lane * 4] = h;
    } else {
        int gi = n2g[gw];
        float* p = &g_graph[gi * HH + lane * 4];
        atomicAdd(p + 0, h.x); atomicAdd(p + 1, h.y);
        atomicAdd(p + 2, h.z); atomicAdd(p + 3, h.w);
    }
}

// ---------------- MLP head: out[g] = relu(g_row @ Wm1 + bm1) @ Wm2 + bm2 ---
__global__ __launch_bounds__(128) void k_mlp(const float* __restrict__ Wm1,
                                             const float* __restrict__ bm1,
                                             const float* __restrict__ Wm2,
                                             const float* __restrict__ bm2,
                                             float* __restrict__ out) {
    __shared__ float gv[HH];
    __shared__ float red[4];
    int t = threadIdx.x, gi = blockIdx.x;
    gv[t] = g_graph[gi * HH + t];
    __syncthreads();
    float s = bm1[t];
#pragma unroll 8
    for (int k = 0; k < HH; k++) s = fmaf(gv[k], Wm1[k * HH + t], s);
    float p = fmaxf(s, 0.f) * Wm2[t];
#pragma unroll
    for (int off = 16; off; off >>= 1) p += __shfl_down_sync(0xffffffffu, p, off);
    if ((t & 31) == 0) red[t >> 5] = p;
    __syncthreads();
    if (t == 0) out[gi] = red[0] + red[1] + red[2] + red[3] + bm2[0];
}

// ---------------- launcher --------------------------------------------------
extern "C" void kernel_launch(void* const* d_in, const int* in_sizes, int n_in,
                              void* d_out, int out_size) {
    const float* x   = (const float*)d_in[0];
    const int*   src = (const int*)d_in[1];
    const int*   dst = (const int*)d_in[2];
    const int*   n2g = (const int*)d_in[3];
    const float* W0  = (const float*)d_in[4];
    const float* b0  = (const float*)d_in[5];
    const float* W1  = (const float*)d_in[6];
    const float* b1  = (const float*)d_in[7];
    const float* W2  = (const float*)d_in[8];
    const float* b2  = (const float*)d_in[9];
    const float* Wm1 = (const float*)d_in[10];
    const float* bm1 = (const float*)d_in[11];
    const float* Wm2 = (const float*)d_in[12];
    const float* bm2 = (const float*)d_in[13];
    float* out = (float*)d_out;

    float *bufA, *bufB;
    cudaGetSymbolAddress((void**)&bufA, g_bufA);
    cudaGetSymbolAddress((void**)&bufB, g_bufB);

    const int TB = 256;
    // graph structure build (rebuilt each launch: determinism rules)
    k_zero<<<(NN + TB - 1) / TB, TB>>>();
    k_hist<<<(EE + TB - 1) / TB, TB>>>(src, dst);
    k_norm<<<(NN + TB - 1) / TB, TB>>>();
    k_scan1<<<NB, 1024>>>();
    k_scan2<<<1, 128>>>();
    k_scan3<<<NB, 1024>>>();
    k_scatter<<<(EE + TB - 1) / TB, TB>>>(src, dst);

    const int gemmGrid = (NN + 127) / 128;
    const int spmmGrid = (NN * 32 + TB - 1) / TB;

    // layer 0
    k_gemm<<<gemmGrid, TB>>>(x, W0, bufA);
    k_spmm<<<spmmGrid, TB>>>(bufA, b0, bufB, n2g, 0);
    // layer 1
    k_gemm<<<gemmGrid, TB>>>(bufB, W1, bufA);
    k_spmm<<<spmmGrid, TB>>>(bufA, b1, bufB, n2g, 0);
    // layer 2 (readout fused into SpMM epilogue)
    k_gemm<<<gemmGrid, TB>>>(bufB, W2, bufA);
    k_spmm<<<spmmGrid, TB>>>(bufA, b2, bufB, n2g, 1);
    // head
    k_mlp<<<GG, 128>>>(Wm1, bm1, Wm2, bm2, out);
}

// round 3
// speedup vs baseline: 1.3660x; 1.3660x over previous
#include <cuda_runtime.h>

#define NN 100000
#define EE 1600000
#define GG 512
#define HH 128
#define NB 98  // ceil(NN/1024)

// ---------------- scratch (device globals: no allocation allowed) ----------
__device__ float g_bufA[NN * HH];   // GEMM output (messages y)
__device__ float g_bufB[NN * HH];   // SpMM output (hidden h)
__device__ int   g_cnt_in[NN];
__device__ int   g_cnt_out[NN];
__device__ int   g_row_ptr[NN + 1];
__device__ int   g_cursor[NN];
__device__ int   g_col[EE];         // src indices grouped by dst (CSR-by-dst)
__device__ float g_norm_in[NN];
__device__ float g_norm_out[NN];
__device__ float g_graph[GG * HH];  // readout accumulator
__device__ int   g_bsum[128];

// ---------------- packed f32x2 helpers (Blackwell FFMA2 via PTX) -----------
__device__ __forceinline__ unsigned long long packf2(float x, float y) {
    unsigned long long r;
    asm("mov.b64 %0, {%1, %2};" : "=l"(r) : "f"(x), "f"(y));
    return r;
}
__device__ __forceinline__ unsigned long long fma2(unsigned long long a,
                                                   unsigned long long b,
                                                   unsigned long long c) {
    unsigned long long d;
    asm("fma.rn.f32x2 %0, %1, %2, %3;" : "=l"(d) : "l"(a), "l"(b), "l"(c));
    return d;
}
__device__ __forceinline__ unsigned long long mul2(unsigned long long a,
                                                   unsigned long long b) {
    unsigned long long d;
    asm("mul.rn.f32x2 %0, %1, %2;" : "=l"(d) : "l"(a), "l"(b));
    return d;
}

// ---------------- build kernels -------------------------------------------
__global__ void k_zero() {
    int i = blockIdx.x * blockDim.x + threadIdx.x;
    if (i < NN) { g_cnt_in[i] = 0; g_cnt_out[i] = 0; g_cursor[i] = 0; }
    if (i < GG * HH) g_graph[i] = 0.f;
}

__global__ void k_hist(const int* __restrict__ src, const int* __restrict__ dst) {
    int i = blockIdx.x * blockDim.x + threadIdx.x;
    if (i < EE) {
        atomicAdd(&g_cnt_out[src[i]], 1);
        atomicAdd(&g_cnt_in[dst[i]], 1);
    }
}

__global__ void k_norm() {
    int i = blockIdx.x * blockDim.x + threadIdx.x;
    if (i < NN) {
        g_norm_out[i] = rsqrtf(fmaxf((float)g_cnt_out[i], 1.f));
        g_norm_in[i]  = rsqrtf(fmaxf((float)g_cnt_in[i], 1.f));
    }
}

__global__ void k_scan1() {
    __shared__ int s[1024];
    int t = threadIdx.x;
    int i = blockIdx.x * 1024 + t;
    int v = (i < NN) ? g_cnt_in[i] : 0;
    s[t] = v;
    __syncthreads();
    for (int off = 1; off < 1024; off <<= 1) {
        int add = (t >= off) ? s[t - off] : 0;
        __syncthreads();
        s[t] += add;
        __syncthreads();
    }
    if (i < NN) g_row_ptr[i] = s[t] - v;     // block-local exclusive
    if (t == 1023) g_bsum[blockIdx.x] = s[1023];
}

__global__ void k_scan2() {
    __shared__ int s[128];
    int t = threadIdx.x;
    int v = (t < NB) ? g_bsum[t] : 0;
    s[t] = v;
    __syncthreads();
    for (int off = 1; off < 128; off <<= 1) {
        int add = (t >= off) ? s[t - off] : 0;
        __syncthreads();
        s[t] += add;
        __syncthreads();
    }
    g_bsum[t] = s[t] - v;                    // exclusive block offsets
}

__global__ void k_scan3() {
    int t = threadIdx.x;
    int i = blockIdx.x * 1024 + t;
    if (i < NN) g_row_ptr[i] += g_bsum[blockIdx.x];
    if (i == 0) g_row_ptr[NN] = EE;
}

__global__ void k_scatter(const int* __restrict__ src, const int* __restrict__ dst) {
    int i = blockIdx.x * blockDim.x + threadIdx.x;
    if (i < EE) {
        int d = dst[i];
        int pos = g_row_ptr[d] + atomicAdd(&g_cursor[d], 1);
        g_col[pos] = src[i];
    }
}

// ---------------- dense GEMM: C[r,:] = norm_out[r] * (A[r,:] @ W) ----------
// BM=128 rows/block, full 128 cols, BK=16, 256 threads, 8 rows x 4 col-pairs
// per thread via packed fma.rn.f32x2 (FFMA2). A tile stored pre-duplicated
// (v,v) so the inner loop has zero packing movs.
__global__ __launch_bounds__(256) void k_gemm(const float* __restrict__ A,
                                              const float* __restrict__ W,
                                              float* __restrict__ C) {
    __shared__ unsigned long long As2[16][128];  // As2[k][m] = (A,A) pair
    __shared__ float Ws[16][128];                // Ws[k][n]
    int tid = threadIdx.x;
    int tx = tid & 15, ty = tid >> 4;
    int row0 = blockIdx.x * 128;

    unsigned long long acc[8][4];
#pragma unroll
    for (int i = 0; i < 8; i++)
#pragma unroll
        for (int j = 0; j < 4; j++) acc[i][j] = 0ull;

    for (int k0 = 0; k0 < HH; k0 += 16) {
#pragma unroll
        for (int j = 0; j < 2; j++) {       // A tile: 128x16 floats -> pairs
            int f = tid * 2 + j;
            int r = f >> 2;
            int c4 = (f & 3) * 4;
            int gr = row0 + r;
            float4 v = make_float4(0.f, 0.f, 0.f, 0.f);
            if (gr < NN) v = *(const float4*)&A[gr * HH + k0 + c4];
            As2[c4 + 0][r] = packf2(v.x, v.x);
            As2[c4 + 1][r] = packf2(v.y, v.y);
            As2[c4 + 2][r] = packf2(v.z, v.z);
            As2[c4 + 3][r] = packf2(v.w, v.w);
        }
#pragma unroll
        for (int j = 0; j < 2; j++) {       // W tile: 16x128 = 512 float4
            int f = tid * 2 + j;
            int r = f >> 5;
            int c4 = (f & 31) * 4;
            *(float4*)&Ws[r][c4] = *(const float4*)&W[(k0 + r) * HH + c4];
        }
        __syncthreads();
#pragma unroll
        for (int kk = 0; kk < 16; kk++) {
            unsigned long long ap[8], wp[4];
            // 8 broadcast pairs for this thread's rows (contiguous, 16B-aligned)
            ulonglong2 a01 = *(const ulonglong2*)&As2[kk][ty * 8 + 0];
            ulonglong2 a23 = *(const ulonglong2*)&As2[kk][ty * 8 + 2];
            ulonglong2 a45 = *(const ulonglong2*)&As2[kk][ty * 8 + 4];
            ulonglong2 a67 = *(const ulonglong2*)&As2[kk][ty * 8 + 6];
            ap[0] = a01.x; ap[1] = a01.y; ap[2] = a23.x; ap[3] = a23.y;
            ap[4] = a45.x; ap[5] = a45.y; ap[6] = a67.x; ap[7] = a67.y;
            // 4 natural column pairs (w[2j], w[2j+1])
            ulonglong2 w01 = *(const ulonglong2*)&Ws[kk][tx * 8 + 0];
            ulonglong2 w23 = *(const ulonglong2*)&Ws[kk][tx * 8 + 4];
            wp[0] = w01.x; wp[1] = w01.y; wp[2] = w23.x; wp[3] = w23.y;
#pragma unroll
            for (int i = 0; i < 8; i++)
#pragma unroll
                for (int j = 0; j < 4; j++)
                    acc[i][j] = fma2(ap[i], wp[j], acc[i][j]);
        }
        __syncthreads();
    }

#pragma unroll
    for (int i = 0; i < 8; i++) {
        int gr = row0 + ty * 8 + i;
        if (gr < NN) {
            unsigned long long scp;
            {
                float sc = g_norm_out[gr];
                scp = packf2(sc, sc);
            }
            ulonglong2 o0, o1;
            o0.x = mul2(acc[i][0], scp); o0.y = mul2(acc[i][1], scp);
            o1.x = mul2(acc[i][2], scp); o1.y = mul2(acc[i][3], scp);
            *(ulonglong2*)&C[gr * HH + tx * 8]     = o0;
            *(ulonglong2*)&C[gr * HH + tx * 8 + 4] = o1;
        }
    }
}

// ---------------- SpMM: h[i] = relu(norm_in[i] * sum_{e:dst=i} y[src_e] + b)
// One warp per destination node; lane owns 4 contiguous features (float4).
__global__ void k_spmm(const float* __restrict__ Y, const float* __restrict__ bias,
                       float* __restrict__ Hout,
                       const int* __restrict__ n2g, int fuse) {
    int gw = (blockIdx.x * blockDim.x + threadIdx.x) >> 5;
    int lane = threadIdx.x & 31;
    if (gw >= NN) return;
    int beg = g_row_ptr[gw], end = g_row_ptr[gw + 1];

    float4 acc = make_float4(0.f, 0.f, 0.f, 0.f);
    int e = beg;
    for (; e + 4 <= end; e += 4) {
        int s0 = g_col[e + 0], s1 = g_col[e + 1];
        int s2 = g_col[e + 2], s3 = g_col[e + 3];
        float4 v0 = *(const float4*)&Y[s0 * HH + lane * 4];
        float4 v1 = *(const float4*)&Y[s1 * HH + lane * 4];
        float4 v2 = *(const float4*)&Y[s2 * HH + lane * 4];
        float4 v3 = *(const float4*)&Y[s3 * HH + lane * 4];
        acc.x += (v0.x + v1.x) + (v2.x + v3.x);
        acc.y += (v0.y + v1.y) + (v2.y + v3.y);
        acc.z += (v0.z + v1.z) + (v2.z + v3.z);
        acc.w += (v0.w + v1.w) + (v2.w + v3.w);
    }
    for (; e < end; e++) {
        int s0 = g_col[e];
        float4 v = *(const float4*)&Y[s0 * HH + lane * 4];
        acc.x += v.x; acc.y += v.y; acc.z += v.z; acc.w += v.w;
    }

    float ni = g_norm_in[gw];
    float4 b = *(const float4*)&bias[lane * 4];
    float4 h;
    h.x = fmaxf(fmaf(acc.x, ni, b.x), 0.f);
    h.y = fmaxf(fmaf(acc.y, ni, b.y), 0.f);
    h.z = fmaxf(fmaf(acc.z, ni, b.z), 0.f);
    h.w = fmaxf(fmaf(acc.w, ni, b.w), 0.f);

    if (!fuse) {
        *(float4*)&Hout[gw * HH + lane * 4] = h;
    } else {
        int gi = n2g[gw];
        float* p = &g_graph[gi * HH + lane * 4];
        atomicAdd(p + 0, h.x); atomicAdd(p + 1, h.y);
        atomicAdd(p + 2, h.z); atomicAdd(p + 3, h.w);
    }
}

// ---------------- MLP head: out[g] = relu(g_row @ Wm1 + bm1) @ Wm2 + bm2 ---
__global__ __launch_bounds__(128) void k_mlp(const float* __restrict__ Wm1,
                                             const float* __restrict__ bm1,
                                             const float* __restrict__ Wm2,
                                             const float* __restrict__ bm2,
                                             float* __restrict__ out) {
    __shared__ float gv[HH];
    __shared__ float red[4];
    int t = threadIdx.x, gi = blockIdx.x;
    gv[t] = g_graph[gi * HH + t];
    __syncthreads();
    float s = bm1[t];
#pragma unroll 8
    for (int k = 0; k < HH; k++) s = fmaf(gv[k], Wm1[k * HH + t], s);
    float p = fmaxf(s, 0.f) * Wm2[t];
#pragma unroll
    for (int off = 16; off; off >>= 1) p += __shfl_down_sync(0xffffffffu, p, off);
    if ((t & 31) == 0) red[t >> 5] = p;
    __syncthreads();
    if (t == 0) out[gi] = red[0] + red[1] + red[2] + red[3] + bm2[0];
}

// ---------------- launcher --------------------------------------------------
extern "C" void kernel_launch(void* const* d_in, const int* in_sizes, int n_in,
                              void* d_out, int out_size) {
    const float* x   = (const float*)d_in[0];
    const int*   src = (const int*)d_in[1];
    const int*   dst = (const int*)d_in[2];
    const int*   n2g = (const int*)d_in[3];
    const float* W0  = (const float*)d_in[4];
    const float* b0  = (const float*)d_in[5];
    const float* W1  = (const float*)d_in[6];
    const float* b1  = (const float*)d_in[7];
    const float* W2  = (const float*)d_in[8];
    const float* b2  = (const float*)d_in[9];
    const float* Wm1 = (const float*)d_in[10];
    const float* bm1 = (const float*)d_in[11];
    const float* Wm2 = (const float*)d_in[12];
    const float* bm2 = (const float*)d_in[13];
    float* out = (float*)d_out;

    float *bufA, *bufB;
    cudaGetSymbolAddress((void**)&bufA, g_bufA);
    cudaGetSymbolAddress((void**)&bufB, g_bufB);

    const int TB = 256;
    // graph structure build (rebuilt each launch: determinism rules)
    k_zero<<<(NN + TB - 1) / TB, TB>>>();
    k_hist<<<(EE + TB - 1) / TB, TB>>>(src, dst);
    k_norm<<<(NN + TB - 1) / TB, TB>>>();
    k_scan1<<<NB, 1024>>>();
    k_scan2<<<1, 128>>>();
    k_scan3<<<NB, 1024>>>();
    k_scatter<<<(EE + TB - 1) / TB, TB>>>(src, dst);

    const int gemmGrid = (NN + 127) / 128;
    const int spmmGrid = (NN * 32 + TB - 1) / TB;

    // layer 0
    k_gemm<<<gemmGrid, TB>>>(x, W0, bufA);
    k_spmm<<<spmmGrid, TB>>>(bufA, b0, bufB, n2g, 0);
    // layer 1
    k_gemm<<<gemmGrid, TB>>>(bufB, W1, bufA);
    k_spmm<<<spmmGrid, TB>>>(bufA, b1, bufB, n2g, 0);
    // layer 2 (readout fused into SpMM epilogue)
    k_gemm<<<gemmGrid, TB>>>(bufB, W2, bufA);
    k_spmm<<<spmmGrid, TB>>>(bufA, b2, bufB, n2g, 1);
    // head
    k_mlp<<<GG, 128>>>(Wm1, bm1, Wm2, bm2, out);
}